// round 4
// baseline (speedup 1.0000x reference)
#include <cuda_runtime.h>
#include <cstdint>
#include <cstddef>

// Problem dims (fixed by the dataset)
#define BB 16
#define TT 512
#define DD 256
#define HH 256
#define GG 1024        // 4H
#define NTOT 65536     // H*H
#define SCALE_ 0.1f

// ---------------------------------------------------------------------------
// Scratch (device-global: sanctioned alternative to cudaMalloc)
// ---------------------------------------------------------------------------
__device__ float g_Wx[(size_t)BB * TT * GG];             // 32 MB: x@W^T + b
__device__ float g_V0[(size_t)4096 * NTOT];              // 1 GB: V rows [0,4096)
__device__ float g_V1[(size_t)4096 * NTOT];              // 1 GB: V rows [4096,8192)
__device__ float g_hbuf[2][BB][HH];                      // double-buffered h

// ===========================================================================
// GEMM 1: V[m][o*256+h'] = sum_d x[m][d] * B_w[o][d][h']   (NN layout)
// A = x [8192 x 256] row-major.  For an n-tile, B slab = B_w + o*65536 + h0,
// layout [d][h'] row-major ld=256.  Tile 128x128, BK=16, double-buffered.
// ===========================================================================
__global__ __launch_bounds__(256) void gemm_v_kernel(
    const float* __restrict__ A, const float* __restrict__ Bw)
{
    __shared__ float As[2][16 * 132];
    __shared__ float Bs[2][16 * 132];
    const int tid = threadIdx.x;
    const int n0  = blockIdx.x * 128;          // global n in [0,65536)
    const int m0  = blockIdx.y * 128;
    const int o   = n0 >> 8;
    const int h0  = n0 & 255;
    const float* Bp = Bw + (size_t)o * NTOT + h0;   // [k][n] ld=256

    const int am = tid >> 1, ah = (tid & 1) * 8;    // A loader: row am, k-off ah
    const int bk = tid >> 4, bn = (tid & 15) * 8;   // B loader: k-row bk, n-off bn
    const int tx = tid & 15, ty = tid >> 4;

    const float* Aptr = A  + (size_t)(m0 + am) * DD + ah;
    const float* Bptr = Bp + (size_t)bk * 256 + bn;

    float4 a0r = *(const float4*)(Aptr);
    float4 a1r = *(const float4*)(Aptr + 4);
    float4 b0r = *(const float4*)(Bptr);
    float4 b1r = *(const float4*)(Bptr + 4);

    float acc[8][8];
#pragma unroll
    for (int i = 0; i < 8; i++)
#pragma unroll
        for (int j = 0; j < 8; j++) acc[i][j] = 0.f;

    {   // stage 0 -> smem (A transposed to [k][m])
        float av[8] = {a0r.x,a0r.y,a0r.z,a0r.w,a1r.x,a1r.y,a1r.z,a1r.w};
#pragma unroll
        for (int i = 0; i < 8; i++) As[0][(ah + i) * 132 + am] = av[i];
        *(float4*)&Bs[0][bk * 132 + bn]     = b0r;
        *(float4*)&Bs[0][bk * 132 + bn + 4] = b1r;
    }
    __syncthreads();

    int p = 0;
#pragma unroll 1
    for (int s = 0; s < 16; s++) {
        if (s < 15) {
            const int k0 = (s + 1) * 16;
            a0r = *(const float4*)(Aptr + k0);
            a1r = *(const float4*)(Aptr + k0 + 4);
            b0r = *(const float4*)(Bptr + (size_t)k0 * 256);
            b1r = *(const float4*)(Bptr + (size_t)k0 * 256 + 4);
        }
#pragma unroll
        for (int kk = 0; kk < 16; kk++) {
            float4 a0 = *(const float4*)&As[p][kk * 132 + ty * 4];
            float4 a1 = *(const float4*)&As[p][kk * 132 + 64 + ty * 4];
            float4 b0 = *(const float4*)&Bs[p][kk * 132 + tx * 4];
            float4 b1 = *(const float4*)&Bs[p][kk * 132 + 64 + tx * 4];
            float ar[8] = {a0.x,a0.y,a0.z,a0.w,a1.x,a1.y,a1.z,a1.w};
            float br[8] = {b0.x,b0.y,b0.z,b0.w,b1.x,b1.y,b1.z,b1.w};
#pragma unroll
            for (int i = 0; i < 8; i++)
#pragma unroll
                for (int j = 0; j < 8; j++) acc[i][j] += ar[i] * br[j];
        }
        if (s < 15) {
            __syncthreads();
            const int q = p ^ 1;
            float av[8] = {a0r.x,a0r.y,a0r.z,a0r.w,a1r.x,a1r.y,a1r.z,a1r.w};
#pragma unroll
            for (int i = 0; i < 8; i++) As[q][(ah + i) * 132 + am] = av[i];
            *(float4*)&Bs[q][bk * 132 + bn]     = b0r;
            *(float4*)&Bs[q][bk * 132 + bn + 4] = b1r;
            __syncthreads();
            p = q;
        }
    }

#pragma unroll
    for (int i = 0; i < 8; i++) {
        const int rr = (i < 4) ? (ty * 4 + i) : (64 + ty * 4 + (i - 4));
        const int m  = m0 + rr;
        float* Vb = (m < 4096 ? g_V0 : g_V1) + (size_t)(m & 4095) * NTOT + n0;
        *(float4*)&Vb[tx * 4]      = make_float4(acc[i][0], acc[i][1], acc[i][2], acc[i][3]);
        *(float4*)&Vb[64 + tx * 4] = make_float4(acc[i][4], acc[i][5], acc[i][6], acc[i][7]);
    }
}

// ===========================================================================
// GEMM 2: Wx[m][g] = sum_d x[m][d] * W_w[g][d] + W_b[g]   (NT layout)
// ===========================================================================
__global__ __launch_bounds__(256) void gemm_wx_kernel(
    const float* __restrict__ A, const float* __restrict__ Ww,
    const float* __restrict__ Wb)
{
    __shared__ float As[2][16 * 132];
    __shared__ float Bs[2][16 * 132];
    const int tid = threadIdx.x;
    const int n0  = blockIdx.x * 128;          // [0,1024)
    const int m0  = blockIdx.y * 128;

    const int am = tid >> 1, ah = (tid & 1) * 8;
    const int wn = tid >> 1, wh = (tid & 1) * 8;   // W loader: row wn, k-off wh
    const int tx = tid & 15, ty = tid >> 4;

    const float* Aptr = A  + (size_t)(m0 + am) * DD + ah;
    const float* Wptr = Ww + (size_t)(n0 + wn) * DD + wh;

    float4 a0r = *(const float4*)(Aptr);
    float4 a1r = *(const float4*)(Aptr + 4);
    float4 b0r = *(const float4*)(Wptr);
    float4 b1r = *(const float4*)(Wptr + 4);

    float acc[8][8];
#pragma unroll
    for (int i = 0; i < 8; i++)
#pragma unroll
        for (int j = 0; j < 8; j++) acc[i][j] = 0.f;

    {
        float av[8] = {a0r.x,a0r.y,a0r.z,a0r.w,a1r.x,a1r.y,a1r.z,a1r.w};
        float bv[8] = {b0r.x,b0r.y,b0r.z,b0r.w,b1r.x,b1r.y,b1r.z,b1r.w};
#pragma unroll
        for (int i = 0; i < 8; i++) {
            As[0][(ah + i) * 132 + am] = av[i];
            Bs[0][(wh + i) * 132 + wn] = bv[i];   // transpose W into [k][n]
        }
    }
    __syncthreads();

    int p = 0;
#pragma unroll 1
    for (int s = 0; s < 16; s++) {
        if (s < 15) {
            const int k0 = (s + 1) * 16;
            a0r = *(const float4*)(Aptr + k0);
            a1r = *(const float4*)(Aptr + k0 + 4);
            b0r = *(const float4*)(Wptr + k0);
            b1r = *(const float4*)(Wptr + k0 + 4);
        }
#pragma unroll
        for (int kk = 0; kk < 16; kk++) {
            float4 a0 = *(const float4*)&As[p][kk * 132 + ty * 4];
            float4 a1 = *(const float4*)&As[p][kk * 132 + 64 + ty * 4];
            float4 b0 = *(const float4*)&Bs[p][kk * 132 + tx * 4];
            float4 b1 = *(const float4*)&Bs[p][kk * 132 + 64 + tx * 4];
            float ar[8] = {a0.x,a0.y,a0.z,a0.w,a1.x,a1.y,a1.z,a1.w};
            float br[8] = {b0.x,b0.y,b0.z,b0.w,b1.x,b1.y,b1.z,b1.w};
#pragma unroll
            for (int i = 0; i < 8; i++)
#pragma unroll
                for (int j = 0; j < 8; j++) acc[i][j] += ar[i] * br[j];
        }
        if (s < 15) {
            __syncthreads();
            const int q = p ^ 1;
            float av[8] = {a0r.x,a0r.y,a0r.z,a0r.w,a1r.x,a1r.y,a1r.z,a1r.w};
            float bv[8] = {b0r.x,b0r.y,b0r.z,b0r.w,b1r.x,b1r.y,b1r.z,b1r.w};
#pragma unroll
            for (int i = 0; i < 8; i++) {
                As[q][(ah + i) * 132 + am] = av[i];
                Bs[q][(wh + i) * 132 + wn] = bv[i];
            }
            __syncthreads();
            p = q;
        }
    }

    float wb0[4], wb1[4];
#pragma unroll
    for (int j = 0; j < 4; j++) {
        wb0[j] = Wb[n0 + tx * 4 + j];
        wb1[j] = Wb[n0 + 64 + tx * 4 + j];
    }
#pragma unroll
    for (int i = 0; i < 8; i++) {
        const int rr = (i < 4) ? (ty * 4 + i) : (64 + ty * 4 + (i - 4));
        const int m  = m0 + rr;
        float* Wo = g_Wx + (size_t)m * GG + n0;
        *(float4*)&Wo[tx * 4] = make_float4(acc[i][0] + wb0[0], acc[i][1] + wb0[1],
                                            acc[i][2] + wb0[2], acc[i][3] + wb0[3]);
        *(float4*)&Wo[64 + tx * 4] = make_float4(acc[i][4] + wb1[0], acc[i][5] + wb1[1],
                                                 acc[i][6] + wb1[2], acc[i][7] + wb1[3]);
    }
}

// ===========================================================================
// Sequential scan. One 8-CTA cluster per batch (16 clusters, grid (8,16)).
// CTA r owns j in [32r, 32r+32): computes its i/f/o/g gate rows (U_w slice
// register-resident, 64 floats/thread at 512 threads) and its 32 m-rows
// (V streamed from HBM). h broadcast via global double buffer + cluster sync.
// ===========================================================================
__global__ void __cluster_dims__(8, 1, 1) __launch_bounds__(512, 1)
scan_kernel(const float* __restrict__ Uw, const float* __restrict__ Ub,
            const float* __restrict__ Bbias, float* __restrict__ out)
{
    __shared__ float h_sm[HH];
    __shared__ float gates_sm[128];
    __shared__ float m_sm[32];
    __shared__ float c_sm[32];
    __shared__ float bb_sm[32];

    const int r     = blockIdx.x;      // CTA rank in cluster
    const int b     = blockIdx.y;      // batch
    const int jbase = r * 32;
    const int t     = threadIdx.x;
    const int qt    = t & 3;           // quarter of the k-range for gates
    const int lg    = t >> 2;          // local gate row [0,128)
    const int row   = (lg >> 5) * HH + jbase + (lg & 31);  // global gate row
    const int r16   = t >> 4;          // m-row [0,32)
    const int l16   = t & 15;

    // register-resident U_w slice: 16 float4 covering k = 4*(i*4+qt)+[0,4)
    float4 U4[16];
#pragma unroll
    for (int i = 0; i < 16; i++)
        U4[i] = *(const float4*)&Uw[(size_t)row * HH + (size_t)(i * 4 + qt) * 4];
    const float ub = Ub[row];

    if (t < HH)  h_sm[t] = 0.f;
    if (t < 32) { c_sm[t] = 0.f; bb_sm[t] = Bbias[jbase + t]; }
    __syncthreads();

    const float4* h4 = (const float4*)h_sm;

    for (int step = 0; step < TT; step++) {
        // ---- V prefetch for this step (independent of h) ----
        const int mrow = b * TT + step;
        const float* Vb = (mrow < 4096 ? g_V0 : g_V1)
                          + (size_t)(mrow & 4095) * NTOT
                          + (size_t)(jbase + r16) * HH;
        const float4* V4 = (const float4*)Vb;
        float4 v[4];
#pragma unroll
        for (int e = 0; e < 4; e++) v[e] = V4[e * 16 + l16];

        float wx = 0.f;
        if (qt == 0) wx = g_Wx[(size_t)mrow * GG + row];

        // ---- gates: dot(U_row, h) split over 4 lanes ----
        float acc = 0.f;
#pragma unroll
        for (int i = 0; i < 16; i++) {
            float4 hh = h4[i * 4 + qt];
            float4 uu = U4[i];
            acc += hh.x * uu.x + hh.y * uu.y + hh.z * uu.z + hh.w * uu.w;
        }
        acc += __shfl_xor_sync(0xffffffffu, acc, 1);
        acc += __shfl_xor_sync(0xffffffffu, acc, 2);

        // ---- m: dot(V_row, h) split over 16 lanes ----
        float macc = 0.f;
#pragma unroll
        for (int e = 0; e < 4; e++) {
            float4 hh = h4[e * 16 + l16];
            macc += v[e].x * hh.x + v[e].y * hh.y + v[e].z * hh.z + v[e].w * hh.w;
        }
#pragma unroll
        for (int off = 8; off > 0; off >>= 1)
            macc += __shfl_xor_sync(0xffffffffu, macc, off);

        if (qt == 0)  gates_sm[lg] = acc + wx + ub;
        if (l16 == 0) m_sm[r16] = macc;
        __syncthreads();

        // ---- cell/hidden update for owned j's ----
        if (t < 32) {
            const int j = jbase + t;
            const float gi = gates_sm[t];
            const float gf = gates_sm[32 + t];
            const float go = gates_sm[64 + t];
            const float gg = gates_sm[96 + t];
            const float iv = 1.f / (1.f + __expf(-gi));
            const float fv = 1.f / (1.f + __expf(-gf));
            const float ov = 1.f / (1.f + __expf(-go));
            const float gv = tanhf(gg);
            const float mv = tanhf(m_sm[t] + bb_sm[t]);
            const float c  = fv * c_sm[t] + iv * gv + SCALE_ * mv;
            c_sm[t] = c;
            const float hn = ov * tanhf(c);
            g_hbuf[step & 1][b][j] = hn;
            out[((size_t)b * TT + step) * HH + j] = hn;
            if (step == TT - 1) {
                const size_t base = (size_t)BB * TT * HH;
                out[base + (size_t)b * HH + j] = hn;
                out[base + (size_t)BB * HH + (size_t)b * HH + j] = c;
            }
            __threadfence();
        }

        // ---- cluster-wide handoff of new h ----
        asm volatile("barrier.cluster.arrive.aligned;" ::: "memory");
        asm volatile("barrier.cluster.wait.aligned;"   ::: "memory");
        if (t < HH) h_sm[t] = g_hbuf[step & 1][b][t];
        __syncthreads();
    }
}

// ===========================================================================
// Launcher (graph-capturable: plain kernel launches on the caller's stream)
// ===========================================================================
extern "C" void kernel_launch(void* const* d_in, const int* in_sizes, int n_in,
                              void* d_out, int out_size)
{
    (void)in_sizes; (void)n_in; (void)out_size;
    const float* x   = (const float*)d_in[0];   // [16,512,256]
    const float* Ww  = (const float*)d_in[1];   // [1024,256]
    const float* Wb  = (const float*)d_in[2];   // [1024]
    const float* Uw  = (const float*)d_in[3];   // [1024,256]
    const float* Ub  = (const float*)d_in[4];   // [1024]
    const float* Bw  = (const float*)d_in[5];   // [256,256,256]
    const float* Bb  = (const float*)d_in[6];   // [256]
    float* out = (float*)d_out;                 // outs | h | c

    gemm_wx_kernel<<<dim3(GG / 128, (BB * TT) / 128), 256>>>(x, Ww, Wb);
    gemm_v_kernel<<<dim3(NTOT / 128, (BB * TT) / 128), 256>>>(x, Bw);
    scan_kernel<<<dim3(8, BB), 512>>>(Uw, Ub, Bb, out);
}